// round 12
// baseline (speedup 1.0000x reference)
#include <cuda_runtime.h>

#define THREADS 256
#define TT 30

typedef unsigned long long ull;

// ---------------- global weight scratch (reordered by prep kernel) ----------------
// [k][u][g] interleaved per layer, float4 quads per (unit, 4 gates)
#define OW1  0        // [80][256]  = 20480
#define OW2  20480    // [96][128]  = 12288
#define OW3  32768    // [32][128]  = 4096   (Whh3)
#define OWI3 36864    // [32][128]  = 4096   (Wih3)
#define OW4  40960    // [96][256]  = 24576  -> total 65536
__device__ __align__(128) float g_w[65536];

// ---------------- shared memory layout (float offsets) ----------------
#define B1o    0      // 256  (interleaved [u][g])
#define B2o    256    // 128
#define B3o    384    // 128
#define B4o    512    // 256
#define BOo    768    // 16
#define WOUTo  784    // [64][32] dup-pairs = 2048
// state [k][row], stride 32, dense (no swizzle needed at 32 rows), double buffered
#define XINo   2832   // 2 x [16][32] = 1024
#define H1o    3856   // 2 x [64][32] = 4096   (P2: h4)
#define H2o    7952   // 2 x [32][32] = 2048   (P2: h3)
#define ZI3o   10000  // 256 threads x 16 floats @ stride 20 = 5120
#define SHF    15120  // 60480 bytes -> 2 blocks/SM

__device__ __forceinline__ void ffma2(ull &acc, ull a, ull b){
    asm("fma.rn.f32x2 %0, %1, %2, %0;" : "+l"(acc) : "l"(a), "l"(b));
}
__device__ __forceinline__ ull bcast2(float w){
    ull r; asm("mov.b64 %0, {%1, %1};" : "=l"(r) : "f"(w)); return r;
}
__device__ __forceinline__ ull pack2(float x, float y){
    ull r; asm("mov.b64 %0, {%1, %2};" : "=l"(r) : "f"(x), "f"(y)); return r;
}
__device__ __forceinline__ float2 unpack2(ull v){
    float2 f; asm("mov.b64 {%0, %1}, %2;" : "=f"(f.x), "=f"(f.y) : "l"(v)); return f;
}
__device__ __forceinline__ float ex2x(float x){
    float e; asm("ex2.approx.f32 %0, %1;" : "=f"(e) : "f"(x)); return e;
}
__device__ __forceinline__ float rcpx(float x){
    float r; asm("rcp.approx.f32 %0, %1;" : "=f"(r) : "f"(x)); return r;
}

// 8-MUFU LSTM activation (gate order i,f,g,o). Returns h, updates c.
__device__ __forceinline__ float act8(float zi, float zf, float zg, float zo, float &c){
    const float K1 = -1.4426950408889634f;
    float ei = ex2x(K1 * zi);
    float ef = ex2x(K1 * zf);
    float eg = ex2x(2.0f * K1 * zg);
    float eo = ex2x(K1 * zo);
    float A = 1.0f + ei, F = 1.0f + ef, G = 1.0f + eg, O = 1.0f + eo;
    float it = (1.0f - eg) * rcpx(A * G);
    float cn = fmaf(c, rcpx(F), it);
    float ec = ex2x(2.0f * K1 * cn);
    float C = 1.0f + ec;
    c = cn;
    return (1.0f - ec) * rcpx(O * C);
}

// acc[j][g][p] += sum_k W[k][u][g] * in[k][r0+2p..]; 4 rows per thread.
// in: SHARED [k][32]; W: GLOBAL (L1-cached)
template<int NU, int NG>
__device__ __forceinline__ void accum(const float* __restrict__ in,
                                      const float* __restrict__ W,
                                      int K, ull (&acc)[NU][4][2], int r0)
{
#pragma unroll 4
    for (int k = 0; k < K; k++) {
        ulonglong2 hA = *reinterpret_cast<const ulonglong2*>(in + k*32 + r0);
        ull hp0 = hA.x, hp1 = hA.y;
#pragma unroll
        for (int j = 0; j < NU; j++) {
            float4 w = __ldg(reinterpret_cast<const float4*>(W + k*NG + j*4));
            ull w0 = bcast2(w.x), w1 = bcast2(w.y), w2 = bcast2(w.z), w3 = bcast2(w.w);
            ffma2(acc[j][0][0], w0, hp0); ffma2(acc[j][0][1], w0, hp1);
            ffma2(acc[j][1][0], w1, hp0); ffma2(acc[j][1][1], w1, hp1);
            ffma2(acc[j][2][0], w2, hp0); ffma2(acc[j][2][1], w2, hp1);
            ffma2(acc[j][3][0], w3, hp0); ffma2(acc[j][3][1], w3, hp1);
        }
    }
}

template<int NU>
__device__ __forceinline__ void init_acc(ull (&acc)[NU][4][2], const float (&b)[NU][4]){
#pragma unroll
    for (int j = 0; j < NU; j++)
#pragma unroll
        for (int g = 0; g < 4; g++) {
            ull bp = bcast2(b[j][g]);
            acc[j][g][0] = bp; acc[j][g][1] = bp;
        }
}

template<int NU>
__device__ __forceinline__ void act_store(ull (&acc)[NU][4][2], float (&c)[NU][4],
                                          float* hdst, int r0)
{
#pragma unroll
    for (int j = 0; j < NU; j++)
#pragma unroll
    for (int p = 0; p < 2; p++) {
        float2 zi = unpack2(acc[j][0][p]);
        float2 zf = unpack2(acc[j][1][p]);
        float2 zg = unpack2(acc[j][2][p]);
        float2 zo = unpack2(acc[j][3][p]);
        float h0 = act8(zi.x, zf.x, zg.x, zo.x, c[j][2*p]);
        float h1 = act8(zi.y, zf.y, zg.y, zo.y, c[j][2*p+1]);
        *reinterpret_cast<ull*>(hdst + j*32 + r0 + 2*p) = pack2(h0, h1);
    }
}

// -------- prep kernel: reorder weights into g_w ([k][u][g] interleaved) --------
__global__ void prep_w(const float* __restrict__ Wih1, const float* __restrict__ Whh1,
                       const float* __restrict__ Wih2, const float* __restrict__ Whh2,
                       const float* __restrict__ Wih3, const float* __restrict__ Whh3,
                       const float* __restrict__ Wih4, const float* __restrict__ Whh4)
{
    int i = blockIdx.x * blockDim.x + threadIdx.x;
    if (i < 20480) {                              // W1: [80][256]
        int k = i >> 8, j = i & 255, u = j >> 2, g = j & 3;
        g_w[OW1 + i] = (k < 16) ? Wih1[(g * 64 + u) * 16 + k]
                                : Whh1[(g * 64 + u) * 64 + (k - 16)];
    } else if (i < 32768) {                       // W2: [96][128]
        int q = i - 20480;
        int k = q >> 7, j = q & 127, u = j >> 2, g = j & 3;
        g_w[OW2 + q] = (k < 64) ? Wih2[(g * 32 + u) * 64 + k]
                                : Whh2[(g * 32 + u) * 32 + (k - 64)];
    } else if (i < 36864) {                       // W3hh: [32][128]
        int q = i - 32768;
        int k = q >> 7, j = q & 127, u = j >> 2, g = j & 3;
        g_w[OW3 + q] = Whh3[(g * 32 + u) * 32 + k];
    } else if (i < 40960) {                       // Wih3: [32][128]
        int q = i - 36864;
        int k = q >> 7, j = q & 127, u = j >> 2, g = j & 3;
        g_w[OWI3 + q] = Wih3[(g * 32 + u) * 32 + k];
    } else if (i < 65536) {                       // W4: [96][256]
        int q = i - 40960;
        int k = q >> 8, j = q & 255, u = j >> 2, g = j & 3;
        g_w[OW4 + q] = (k < 32) ? Wih4[(g * 64 + u) * 32 + k]
                                : Whh4[(g * 64 + u) * 64 + (k - 32)];
    }
}

__global__ void __launch_bounds__(THREADS, 2)
lstm_ae(const float* __restrict__ x,
        const float* __restrict__ b1, const float* __restrict__ b2,
        const float* __restrict__ b3, const float* __restrict__ b4,
        const float* __restrict__ Wout, const float* __restrict__ bout,
        float* __restrict__ out)
{
    extern __shared__ float sh[];
    const int tid = threadIdx.x;
    const int wid = tid >> 5;
    const bool grpA = ((wid >> 2) & 1) == 0;
    const long row0 = (long)blockIdx.x * 32;

    const int u0a = (tid >> 3) * 2;     // H=64 layers: 2 units
    const int u0b = (tid >> 3);         // H=32 layers: 1 unit
    const int r0  = (tid & 7) * 4;      // 4 rows per thread

    // x-io mapping: row = tid&31, feature pair = (tid>>5)*2
    const int xr  = tid & 31;
    const int xf0 = (tid >> 5) * 2;
    // projection mapping: fo = tid&15, row pair = 2*(tid>>4)
    const int fo = tid & 15, rb = tid >> 4;

    const float* gW1  = g_w + OW1;
    const float* gW2  = g_w + OW2;
    const float* gW3  = g_w + OW3;
    const float* gWI3 = g_w + OWI3;
    const float* gW4  = g_w + OW4;

    // ---- biases + dup-Wout staging, zero state ----
    if (tid < 256) { int u = tid >> 2, g = tid & 3; sh[B1o + tid] = b1[g * 64 + u]; }
    if (tid < 128) { int u = tid >> 2, g = tid & 3; sh[B2o + tid] = b2[g * 32 + u]; }
    if (tid < 128) { int u = tid >> 2, g = tid & 3; sh[B3o + tid] = b3[g * 32 + u]; }
    if (tid < 256) { int u = tid >> 2, g = tid & 3; sh[B4o + tid] = b4[g * 64 + u]; }
    if (tid < 16)  sh[BOo + tid] = bout[tid];
    for (int i = tid; i < 2048; i += THREADS) {            // dup pairs
        int j = i >> 5, f = (i & 31) >> 1;
        sh[WOUTo + i] = Wout[f * 64 + j];
    }
    for (int i = tid; i < 2048; i += THREADS) sh[H1o + i] = 0.f;   // h1 buf0
    for (int i = tid; i < 1024; i += THREADS) sh[H2o + i] = 0.f;   // h2 buf0
    {   // x(0) -> XIN buf0
        float2 gx = __ldcs(reinterpret_cast<const float2*>(x + (row0 + xr) * (TT * 16) + xf0));
        sh[XINo + (xf0    ) * 32 + xr] = gx.x;
        sh[XINo + (xf0 + 1) * 32 + xr] = gx.y;
    }
    __syncthreads();

    float b1s[2][4], b2s[1][4];
#pragma unroll
    for (int j = 0; j < 2; j++)
#pragma unroll
        for (int g = 0; g < 4; g++) b1s[j][g] = sh[B1o + (u0a + j) * 4 + g];
#pragma unroll
    for (int g = 0; g < 4; g++) b2s[0][g] = sh[B2o + u0b * 4 + g];

    float c1[2][4], c2[1][4];
#pragma unroll
    for (int j = 0; j < 2; j++)
#pragma unroll
        for (int q = 0; q < 4; q++) c1[j][q] = 0.f;
#pragma unroll
    for (int q = 0; q < 4; q++) c2[0][q] = 0.f;

    // ---- phase 1: encoder. accL1 enters each t as b1 + Whh1@h1(t-1). ----
    ull accL1[2][4][2], accL2[1][4][2];
    init_acc<2>(accL1, b1s);                 // h1(-1) = 0

    for (int t = 0; t < TT; t++) {
        const int p = t & 1;
        float2 gx;
        const bool pf = (t + 1 < TT);
        if (pf) gx = __ldcs(reinterpret_cast<const float2*>(
            x + (row0 + xr) * (TT * 16) + (t + 1) * 16 + xf0));
        accum<2, 256>(sh + XINo + p * 512, gW1 + u0a * 4, 16, accL1, r0);
        if (pf) {
            float* xb = sh + XINo + (p ^ 1) * 512;
            xb[(xf0    ) * 32 + xr] = gx.x;
            xb[(xf0 + 1) * 32 + xr] = gx.y;
        }
        if (grpA) {
            act_store<2>(accL1, c1, sh + H1o + (p ^ 1) * 2048 + u0a * 32, r0);
            init_acc<1>(accL2, b2s);
            accum<1, 128>(sh + H2o + p * 1024, gW2 + 64 * 128 + u0b * 4, 32, accL2, r0);
        } else {
            init_acc<1>(accL2, b2s);
            accum<1, 128>(sh + H2o + p * 1024, gW2 + 64 * 128 + u0b * 4, 32, accL2, r0);
            act_store<2>(accL1, c1, sh + H1o + (p ^ 1) * 2048 + u0a * 32, r0);
        }
        __syncthreads();
        accum<1, 128>(sh + H1o + (p ^ 1) * 2048, gW2 + u0b * 4, 64, accL2, r0);
        if (grpA) {
            act_store<1>(accL2, c2, sh + H2o + (p ^ 1) * 1024 + u0b * 32, r0);
            init_acc<2>(accL1, b1s);
            accum<2, 256>(sh + H1o + (p ^ 1) * 2048, gW1 + 16 * 256 + u0a * 4, 64, accL1, r0);
        } else {
            init_acc<2>(accL1, b1s);
            accum<2, 256>(sh + H1o + (p ^ 1) * 2048, gW1 + 16 * 256 + u0a * 4, 64, accL1, r0);
            act_store<1>(accL2, c2, sh + H2o + (p ^ 1) * 1024 + u0b * 32, r0);
        }
        __syncthreads();
    }
    // latent = h2(29) in H2 buf 0

    // zin3 = Wih3 @ latent + b3 (constant over t) -> padded smem (stride 20)
    {
        float b3s[1][4];
#pragma unroll
        for (int g = 0; g < 4; g++) b3s[0][g] = sh[B3o + u0b * 4 + g];
        ull z3[1][4][2];
        init_acc<1>(z3, b3s);
        accum<1, 128>(sh + H2o, gWI3 + u0b * 4, 32, z3, r0);
        ull* zp = reinterpret_cast<ull*>(sh + ZI3o + tid * 20);
#pragma unroll
        for (int g = 0; g < 4; g++) {
            zp[g * 2 + 0] = z3[0][g][0];
            zp[g * 2 + 1] = z3[0][g][1];
        }
        __syncthreads();   // latent reads done; zin3 visible
        for (int i = tid; i < 1024; i += THREADS) sh[H2o + i] = 0.f;  // h3 buf0
        for (int i = tid; i < 2048; i += THREADS) sh[H1o + i] = 0.f;  // h4 buf0
    }
    __syncthreads();

    float b4s[2][4];
#pragma unroll
    for (int j = 0; j < 2; j++)
#pragma unroll
        for (int g = 0; g < 4; g++) b4s[j][g] = sh[B4o + (u0a + j) * 4 + g];
    const ull boutp = bcast2(sh[BOo + fo]);
    const ull* zin = reinterpret_cast<const ull*>(sh + ZI3o + tid * 20);

    float c3[1][4], c4[2][4];
#pragma unroll
    for (int q = 0; q < 4; q++) c3[0][q] = 0.f;
#pragma unroll
    for (int j = 0; j < 2; j++)
#pragma unroll
        for (int q = 0; q < 4; q++) c4[j][q] = 0.f;

    // ---- phase 2: decoder. accL3 enters each t as zin3 + Whh3@h3(t-1). ----
    ull accL3[1][4][2], accL4[2][4][2];
#pragma unroll
    for (int g = 0; g < 4; g++) {
        accL3[0][g][0] = zin[g * 2 + 0];
        accL3[0][g][1] = zin[g * 2 + 1];
    }

    for (int t = 0; t < TT; t++) {
        const int p = t & 1;
        if (grpA) {
            act_store<1>(accL3, c3, sh + H2o + (p ^ 1) * 1024 + u0b * 32, r0);
            init_acc<2>(accL4, b4s);
            accum<2, 256>(sh + H1o + p * 2048, gW4 + 32 * 256 + u0a * 4, 64, accL4, r0);
        } else {
            init_acc<2>(accL4, b4s);
            accum<2, 256>(sh + H1o + p * 2048, gW4 + 32 * 256 + u0a * 4, 64, accL4, r0);
        }
        if (t > 0) {   // projection of h4(t-1) from H1[p], overlapped
            const float* h4 = sh + H1o + p * 2048;
            ull a0 = boutp;
#pragma unroll 8
            for (int j = 0; j < 64; j++) {
                ull w  = *reinterpret_cast<const ull*>(sh + WOUTo + j * 32 + 2 * fo);
                ull hq = *reinterpret_cast<const ull*>(h4 + j * 32 + 2 * rb);
                ffma2(a0, w, hq);
            }
            float2 y = unpack2(a0);
            long ob = (row0 + rb * 2) * (TT * 16) + (t - 1) * 16 + fo;
            out[ob]           = y.x;
            out[ob + TT * 16] = y.y;
        }
        if (!grpA)
            act_store<1>(accL3, c3, sh + H2o + (p ^ 1) * 1024 + u0b * 32, r0);
        __syncthreads();
        accum<2, 256>(sh + H2o + (p ^ 1) * 1024, gW4 + u0a * 4, 32, accL4, r0);
        if (grpA) {
            act_store<2>(accL4, c4, sh + H1o + (p ^ 1) * 2048 + u0a * 32, r0);
#pragma unroll
            for (int g = 0; g < 4; g++) {
                accL3[0][g][0] = zin[g * 2 + 0];
                accL3[0][g][1] = zin[g * 2 + 1];
            }
            accum<1, 128>(sh + H2o + (p ^ 1) * 1024, gW3 + u0b * 4, 32, accL3, r0);
        } else {
#pragma unroll
            for (int g = 0; g < 4; g++) {
                accL3[0][g][0] = zin[g * 2 + 0];
                accL3[0][g][1] = zin[g * 2 + 1];
            }
            accum<1, 128>(sh + H2o + (p ^ 1) * 1024, gW3 + u0b * 4, 32, accL3, r0);
            act_store<2>(accL4, c4, sh + H1o + (p ^ 1) * 2048 + u0a * 32, r0);
        }
        __syncthreads();
    }
    // final projection: h4(29) in H1 buf 0
    {
        const float* h4 = sh + H1o;
        ull a0 = boutp;
#pragma unroll 8
        for (int j = 0; j < 64; j++) {
            ull w  = *reinterpret_cast<const ull*>(sh + WOUTo + j * 32 + 2 * fo);
            ull hq = *reinterpret_cast<const ull*>(h4 + j * 32 + 2 * rb);
            ffma2(a0, w, hq);
        }
        float2 y = unpack2(a0);
        long ob = (row0 + rb * 2) * (TT * 16) + (TT - 1) * 16 + fo;
        out[ob]           = y.x;
        out[ob + TT * 16] = y.y;
    }
}

extern "C" void kernel_launch(void* const* d_in, const int* in_sizes, int n_in,
                              void* d_out, int out_size)
{
    const float* x    = (const float*)d_in[0];
    const float* Wih1 = (const float*)d_in[1];
    const float* Whh1 = (const float*)d_in[2];
    const float* b1   = (const float*)d_in[3];
    const float* Wih2 = (const float*)d_in[4];
    const float* Whh2 = (const float*)d_in[5];
    const float* b2   = (const float*)d_in[6];
    const float* Wih3 = (const float*)d_in[7];
    const float* Whh3 = (const float*)d_in[8];
    const float* b3   = (const float*)d_in[9];
    const float* Wih4 = (const float*)d_in[10];
    const float* Whh4 = (const float*)d_in[11];
    const float* b4   = (const float*)d_in[12];
    const float* Wout = (const float*)d_in[13];
    const float* bout = (const float*)d_in[14];
    float* out = (float*)d_out;

    prep_w<<<256, 256>>>(Wih1, Whh1, Wih2, Whh2, Wih3, Whh3, Wih4, Whh4);

    cudaFuncSetAttribute(lstm_ae, cudaFuncAttributeMaxDynamicSharedMemorySize,
                         SHF * (int)sizeof(float));
    lstm_ae<<<256, THREADS, SHF * sizeof(float)>>>(
        x, b1, b2, b3, b4, Wout, bout, out);
}

// round 13
// speedup vs baseline: 1.0022x; 1.0022x over previous
#include <cuda_runtime.h>

#define THREADS 256
#define TT 30

typedef unsigned long long ull;

// ---------------- global weight scratch (reordered by prep kernel) ----------------
// [k][u][g] interleaved per layer, float4 quads per (unit, 4 gates)
#define OW1  0        // [80][256]  = 20480
#define OW2  20480    // [96][128]  = 12288
#define OW3  32768    // [32][128]  = 4096   (Whh3)
#define OWI3 36864    // [32][128]  = 4096   (Wih3)
#define OW4  40960    // [96][256]  = 24576  -> total 65536
__device__ __align__(128) float g_w[65536];

// ---------------- shared memory layout (float offsets) ----------------
#define B1o    0      // 256  (interleaved [u][g])
#define B2o    256    // 128
#define B3o    384    // 128
#define B4o    512    // 256
#define BOo    768    // 16
#define WOUTo  784    // [64][32] dup-pairs = 2048
// state [k][row], stride 32, dense (no swizzle needed at 32 rows), double buffered
#define XINo   2832   // 2 x [16][32] = 1024
#define H1o    3856   // 2 x [64][32] = 4096   (P2: h4)
#define H2o    7952   // 2 x [32][32] = 2048   (P2: h3)
#define ZI3o   10000  // 256 threads x 16 floats @ stride 20 = 5120
#define SHF    15120  // 60480 bytes -> 2 blocks/SM

__device__ __forceinline__ void ffma2(ull &acc, ull a, ull b){
    asm("fma.rn.f32x2 %0, %1, %2, %0;" : "+l"(acc) : "l"(a), "l"(b));
}
__device__ __forceinline__ ull bcast2(float w){
    ull r; asm("mov.b64 %0, {%1, %1};" : "=l"(r) : "f"(w)); return r;
}
__device__ __forceinline__ ull pack2(float x, float y){
    ull r; asm("mov.b64 %0, {%1, %2};" : "=l"(r) : "f"(x), "f"(y)); return r;
}
__device__ __forceinline__ float2 unpack2(ull v){
    float2 f; asm("mov.b64 {%0, %1}, %2;" : "=f"(f.x), "=f"(f.y) : "l"(v)); return f;
}
__device__ __forceinline__ float ex2x(float x){
    float e; asm("ex2.approx.f32 %0, %1;" : "=f"(e) : "f"(x)); return e;
}
__device__ __forceinline__ float rcpx(float x){
    float r; asm("rcp.approx.f32 %0, %1;" : "=f"(r) : "f"(x)); return r;
}

// 8-MUFU LSTM activation (gate order i,f,g,o). Returns h, updates c.
__device__ __forceinline__ float act8(float zi, float zf, float zg, float zo, float &c){
    const float K1 = -1.4426950408889634f;
    float ei = ex2x(K1 * zi);
    float ef = ex2x(K1 * zf);
    float eg = ex2x(2.0f * K1 * zg);
    float eo = ex2x(K1 * zo);
    float A = 1.0f + ei, F = 1.0f + ef, G = 1.0f + eg, O = 1.0f + eo;
    float it = (1.0f - eg) * rcpx(A * G);
    float cn = fmaf(c, rcpx(F), it);
    float ec = ex2x(2.0f * K1 * cn);
    float C = 1.0f + ec;
    c = cn;
    return (1.0f - ec) * rcpx(O * C);
}

// acc[j][g][p] += sum_k W[k][u][g] * in[k][r0+2p..]; 4 rows per thread.
// in: SHARED [k][32]; W: GLOBAL (L1-cached)
template<int NU, int NG>
__device__ __forceinline__ void accum(const float* __restrict__ in,
                                      const float* __restrict__ W,
                                      int K, ull (&acc)[NU][4][2], int r0)
{
#pragma unroll 4
    for (int k = 0; k < K; k++) {
        ulonglong2 hA = *reinterpret_cast<const ulonglong2*>(in + k*32 + r0);
        ull hp0 = hA.x, hp1 = hA.y;
#pragma unroll
        for (int j = 0; j < NU; j++) {
            float4 w = __ldg(reinterpret_cast<const float4*>(W + k*NG + j*4));
            ull w0 = bcast2(w.x), w1 = bcast2(w.y), w2 = bcast2(w.z), w3 = bcast2(w.w);
            ffma2(acc[j][0][0], w0, hp0); ffma2(acc[j][0][1], w0, hp1);
            ffma2(acc[j][1][0], w1, hp0); ffma2(acc[j][1][1], w1, hp1);
            ffma2(acc[j][2][0], w2, hp0); ffma2(acc[j][2][1], w2, hp1);
            ffma2(acc[j][3][0], w3, hp0); ffma2(acc[j][3][1], w3, hp1);
        }
    }
}

template<int NU>
__device__ __forceinline__ void init_acc(ull (&acc)[NU][4][2], const float (&b)[NU][4]){
#pragma unroll
    for (int j = 0; j < NU; j++)
#pragma unroll
        for (int g = 0; g < 4; g++) {
            ull bp = bcast2(b[j][g]);
            acc[j][g][0] = bp; acc[j][g][1] = bp;
        }
}

template<int NU>
__device__ __forceinline__ void act_store(ull (&acc)[NU][4][2], float (&c)[NU][4],
                                          float* hdst, int r0)
{
#pragma unroll
    for (int j = 0; j < NU; j++)
#pragma unroll
    for (int p = 0; p < 2; p++) {
        float2 zi = unpack2(acc[j][0][p]);
        float2 zf = unpack2(acc[j][1][p]);
        float2 zg = unpack2(acc[j][2][p]);
        float2 zo = unpack2(acc[j][3][p]);
        float h0 = act8(zi.x, zf.x, zg.x, zo.x, c[j][2*p]);
        float h1 = act8(zi.y, zf.y, zg.y, zo.y, c[j][2*p+1]);
        *reinterpret_cast<ull*>(hdst + j*32 + r0 + 2*p) = pack2(h0, h1);
    }
}

// -------- prep kernel: reorder weights into g_w ([k][u][g] interleaved) --------
__global__ void prep_w(const float* __restrict__ Wih1, const float* __restrict__ Whh1,
                       const float* __restrict__ Wih2, const float* __restrict__ Whh2,
                       const float* __restrict__ Wih3, const float* __restrict__ Whh3,
                       const float* __restrict__ Wih4, const float* __restrict__ Whh4)
{
    int i = blockIdx.x * blockDim.x + threadIdx.x;
    if (i < 20480) {                              // W1: [80][256]
        int k = i >> 8, j = i & 255, u = j >> 2, g = j & 3;
        g_w[OW1 + i] = (k < 16) ? Wih1[(g * 64 + u) * 16 + k]
                                : Whh1[(g * 64 + u) * 64 + (k - 16)];
    } else if (i < 32768) {                       // W2: [96][128]
        int q = i - 20480;
        int k = q >> 7, j = q & 127, u = j >> 2, g = j & 3;
        g_w[OW2 + q] = (k < 64) ? Wih2[(g * 32 + u) * 64 + k]
                                : Whh2[(g * 32 + u) * 32 + (k - 64)];
    } else if (i < 36864) {                       // W3hh: [32][128]
        int q = i - 32768;
        int k = q >> 7, j = q & 127, u = j >> 2, g = j & 3;
        g_w[OW3 + q] = Whh3[(g * 32 + u) * 32 + k];
    } else if (i < 40960) {                       // Wih3: [32][128]
        int q = i - 36864;
        int k = q >> 7, j = q & 127, u = j >> 2, g = j & 3;
        g_w[OWI3 + q] = Wih3[(g * 32 + u) * 32 + k];
    } else if (i < 65536) {                       // W4: [96][256]
        int q = i - 40960;
        int k = q >> 8, j = q & 255, u = j >> 2, g = j & 3;
        g_w[OW4 + q] = (k < 32) ? Wih4[(g * 64 + u) * 32 + k]
                                : Whh4[(g * 64 + u) * 64 + (k - 32)];
    }
}

__global__ void __launch_bounds__(THREADS, 2)
lstm_ae(const float* __restrict__ x,
        const float* __restrict__ b1, const float* __restrict__ b2,
        const float* __restrict__ b3, const float* __restrict__ b4,
        const float* __restrict__ Wout, const float* __restrict__ bout,
        float* __restrict__ out)
{
    extern __shared__ float sh[];
    const int tid = threadIdx.x;
    const int wid = tid >> 5;
    const bool grpA = ((wid >> 2) & 1) == 0;
    const long row0 = (long)blockIdx.x * 32;

    const int u0a = (tid >> 3) * 2;     // H=64 layers: 2 units
    const int u0b = (tid >> 3);         // H=32 layers: 1 unit
    const int r0  = (tid & 7) * 4;      // 4 rows per thread

    // x-io mapping: row = tid&31, feature pair = (tid>>5)*2
    const int xr  = tid & 31;
    const int xf0 = (tid >> 5) * 2;
    // projection mapping: fo = tid&15, row pair = 2*(tid>>4)
    const int fo = tid & 15, rb = tid >> 4;

    const float* gW1  = g_w + OW1;
    const float* gW2  = g_w + OW2;
    const float* gW3  = g_w + OW3;
    const float* gWI3 = g_w + OWI3;
    const float* gW4  = g_w + OW4;

    // ---- biases + dup-Wout staging, zero state ----
    if (tid < 256) { int u = tid >> 2, g = tid & 3; sh[B1o + tid] = b1[g * 64 + u]; }
    if (tid < 128) { int u = tid >> 2, g = tid & 3; sh[B2o + tid] = b2[g * 32 + u]; }
    if (tid < 128) { int u = tid >> 2, g = tid & 3; sh[B3o + tid] = b3[g * 32 + u]; }
    if (tid < 256) { int u = tid >> 2, g = tid & 3; sh[B4o + tid] = b4[g * 64 + u]; }
    if (tid < 16)  sh[BOo + tid] = bout[tid];
    for (int i = tid; i < 2048; i += THREADS) {            // dup pairs
        int j = i >> 5, f = (i & 31) >> 1;
        sh[WOUTo + i] = Wout[f * 64 + j];
    }
    for (int i = tid; i < 2048; i += THREADS) sh[H1o + i] = 0.f;   // h1 buf0
    for (int i = tid; i < 1024; i += THREADS) sh[H2o + i] = 0.f;   // h2 buf0
    {   // x(0) -> XIN buf0
        float2 gx = __ldcs(reinterpret_cast<const float2*>(x + (row0 + xr) * (TT * 16) + xf0));
        sh[XINo + (xf0    ) * 32 + xr] = gx.x;
        sh[XINo + (xf0 + 1) * 32 + xr] = gx.y;
    }
    __syncthreads();

    float b1s[2][4], b2s[1][4];
#pragma unroll
    for (int j = 0; j < 2; j++)
#pragma unroll
        for (int g = 0; g < 4; g++) b1s[j][g] = sh[B1o + (u0a + j) * 4 + g];
#pragma unroll
    for (int g = 0; g < 4; g++) b2s[0][g] = sh[B2o + u0b * 4 + g];

    float c1[2][4], c2[1][4];
#pragma unroll
    for (int j = 0; j < 2; j++)
#pragma unroll
        for (int q = 0; q < 4; q++) c1[j][q] = 0.f;
#pragma unroll
    for (int q = 0; q < 4; q++) c2[0][q] = 0.f;

    // ---- phase 1: encoder. accL1 enters each t as b1 + Whh1@h1(t-1). ----
    ull accL1[2][4][2], accL2[1][4][2];
    init_acc<2>(accL1, b1s);                 // h1(-1) = 0

    for (int t = 0; t < TT; t++) {
        const int p = t & 1;
        float2 gx;
        const bool pf = (t + 1 < TT);
        if (pf) gx = __ldcs(reinterpret_cast<const float2*>(
            x + (row0 + xr) * (TT * 16) + (t + 1) * 16 + xf0));
        accum<2, 256>(sh + XINo + p * 512, gW1 + u0a * 4, 16, accL1, r0);
        if (pf) {
            float* xb = sh + XINo + (p ^ 1) * 512;
            xb[(xf0    ) * 32 + xr] = gx.x;
            xb[(xf0 + 1) * 32 + xr] = gx.y;
        }
        if (grpA) {
            act_store<2>(accL1, c1, sh + H1o + (p ^ 1) * 2048 + u0a * 32, r0);
            init_acc<1>(accL2, b2s);
            accum<1, 128>(sh + H2o + p * 1024, gW2 + 64 * 128 + u0b * 4, 32, accL2, r0);
        } else {
            init_acc<1>(accL2, b2s);
            accum<1, 128>(sh + H2o + p * 1024, gW2 + 64 * 128 + u0b * 4, 32, accL2, r0);
            act_store<2>(accL1, c1, sh + H1o + (p ^ 1) * 2048 + u0a * 32, r0);
        }
        __syncthreads();
        accum<1, 128>(sh + H1o + (p ^ 1) * 2048, gW2 + u0b * 4, 64, accL2, r0);
        if (grpA) {
            act_store<1>(accL2, c2, sh + H2o + (p ^ 1) * 1024 + u0b * 32, r0);
            init_acc<2>(accL1, b1s);
            accum<2, 256>(sh + H1o + (p ^ 1) * 2048, gW1 + 16 * 256 + u0a * 4, 64, accL1, r0);
        } else {
            init_acc<2>(accL1, b1s);
            accum<2, 256>(sh + H1o + (p ^ 1) * 2048, gW1 + 16 * 256 + u0a * 4, 64, accL1, r0);
            act_store<1>(accL2, c2, sh + H2o + (p ^ 1) * 1024 + u0b * 32, r0);
        }
        __syncthreads();
    }
    // latent = h2(29) in H2 buf 0

    // zin3 = Wih3 @ latent + b3 (constant over t) -> padded smem (stride 20)
    {
        float b3s[1][4];
#pragma unroll
        for (int g = 0; g < 4; g++) b3s[0][g] = sh[B3o + u0b * 4 + g];
        ull z3[1][4][2];
        init_acc<1>(z3, b3s);
        accum<1, 128>(sh + H2o, gWI3 + u0b * 4, 32, z3, r0);
        ull* zp = reinterpret_cast<ull*>(sh + ZI3o + tid * 20);
#pragma unroll
        for (int g = 0; g < 4; g++) {
            zp[g * 2 + 0] = z3[0][g][0];
            zp[g * 2 + 1] = z3[0][g][1];
        }
        __syncthreads();   // latent reads done; zin3 visible
        for (int i = tid; i < 1024; i += THREADS) sh[H2o + i] = 0.f;  // h3 buf0
        for (int i = tid; i < 2048; i += THREADS) sh[H1o + i] = 0.f;  // h4 buf0
    }
    __syncthreads();

    float b4s[2][4];
#pragma unroll
    for (int j = 0; j < 2; j++)
#pragma unroll
        for (int g = 0; g < 4; g++) b4s[j][g] = sh[B4o + (u0a + j) * 4 + g];
    const ull boutp = bcast2(sh[BOo + fo]);
    const ull* zin = reinterpret_cast<const ull*>(sh + ZI3o + tid * 20);

    float c3[1][4], c4[2][4];
#pragma unroll
    for (int q = 0; q < 4; q++) c3[0][q] = 0.f;
#pragma unroll
    for (int j = 0; j < 2; j++)
#pragma unroll
        for (int q = 0; q < 4; q++) c4[j][q] = 0.f;

    // ---- phase 2: decoder. accL3 enters each t as zin3 + Whh3@h3(t-1). ----
    ull accL3[1][4][2], accL4[2][4][2];
#pragma unroll
    for (int g = 0; g < 4; g++) {
        accL3[0][g][0] = zin[g * 2 + 0];
        accL3[0][g][1] = zin[g * 2 + 1];
    }

    for (int t = 0; t < TT; t++) {
        const int p = t & 1;
        if (grpA) {
            act_store<1>(accL3, c3, sh + H2o + (p ^ 1) * 1024 + u0b * 32, r0);
            init_acc<2>(accL4, b4s);
            accum<2, 256>(sh + H1o + p * 2048, gW4 + 32 * 256 + u0a * 4, 64, accL4, r0);
        } else {
            init_acc<2>(accL4, b4s);
            accum<2, 256>(sh + H1o + p * 2048, gW4 + 32 * 256 + u0a * 4, 64, accL4, r0);
        }
        if (t > 0) {   // projection of h4(t-1) from H1[p], overlapped
            const float* h4 = sh + H1o + p * 2048;
            ull a0 = boutp;
#pragma unroll 8
            for (int j = 0; j < 64; j++) {
                ull w  = *reinterpret_cast<const ull*>(sh + WOUTo + j * 32 + 2 * fo);
                ull hq = *reinterpret_cast<const ull*>(h4 + j * 32 + 2 * rb);
                ffma2(a0, w, hq);
            }
            float2 y = unpack2(a0);
            long ob = (row0 + rb * 2) * (TT * 16) + (t - 1) * 16 + fo;
            out[ob]           = y.x;
            out[ob + TT * 16] = y.y;
        }
        if (!grpA)
            act_store<1>(accL3, c3, sh + H2o + (p ^ 1) * 1024 + u0b * 32, r0);
        __syncthreads();
        accum<2, 256>(sh + H2o + (p ^ 1) * 1024, gW4 + u0a * 4, 32, accL4, r0);
        if (grpA) {
            act_store<2>(accL4, c4, sh + H1o + (p ^ 1) * 2048 + u0a * 32, r0);
#pragma unroll
            for (int g = 0; g < 4; g++) {
                accL3[0][g][0] = zin[g * 2 + 0];
                accL3[0][g][1] = zin[g * 2 + 1];
            }
            accum<1, 128>(sh + H2o + (p ^ 1) * 1024, gW3 + u0b * 4, 32, accL3, r0);
        } else {
#pragma unroll
            for (int g = 0; g < 4; g++) {
                accL3[0][g][0] = zin[g * 2 + 0];
                accL3[0][g][1] = zin[g * 2 + 1];
            }
            accum<1, 128>(sh + H2o + (p ^ 1) * 1024, gW3 + u0b * 4, 32, accL3, r0);
            act_store<2>(accL4, c4, sh + H1o + (p ^ 1) * 2048 + u0a * 32, r0);
        }
        __syncthreads();
    }
    // final projection: h4(29) in H1 buf 0
    {
        const float* h4 = sh + H1o;
        ull a0 = boutp;
#pragma unroll 8
        for (int j = 0; j < 64; j++) {
            ull w  = *reinterpret_cast<const ull*>(sh + WOUTo + j * 32 + 2 * fo);
            ull hq = *reinterpret_cast<const ull*>(h4 + j * 32 + 2 * rb);
            ffma2(a0, w, hq);
        }
        float2 y = unpack2(a0);
        long ob = (row0 + rb * 2) * (TT * 16) + (TT - 1) * 16 + fo;
        out[ob]           = y.x;
        out[ob + TT * 16] = y.y;
    }
}

extern "C" void kernel_launch(void* const* d_in, const int* in_sizes, int n_in,
                              void* d_out, int out_size)
{
    const float* x    = (const float*)d_in[0];
    const float* Wih1 = (const float*)d_in[1];
    const float* Whh1 = (const float*)d_in[2];
    const float* b1   = (const float*)d_in[3];
    const float* Wih2 = (const float*)d_in[4];
    const float* Whh2 = (const float*)d_in[5];
    const float* b2   = (const float*)d_in[6];
    const float* Wih3 = (const float*)d_in[7];
    const float* Whh3 = (const float*)d_in[8];
    const float* b3   = (const float*)d_in[9];
    const float* Wih4 = (const float*)d_in[10];
    const float* Whh4 = (const float*)d_in[11];
    const float* b4   = (const float*)d_in[12];
    const float* Wout = (const float*)d_in[13];
    const float* bout = (const float*)d_in[14];
    float* out = (float*)d_out;

    prep_w<<<256, 256>>>(Wih1, Whh1, Wih2, Whh2, Wih3, Whh3, Wih4, Whh4);

    cudaFuncSetAttribute(lstm_ae, cudaFuncAttributeMaxDynamicSharedMemorySize,
                         SHF * (int)sizeof(float));
    lstm_ae<<<256, THREADS, SHF * sizeof(float)>>>(
        x, b1, b2, b3, b4, Wout, bout, out);
}

// round 14
// speedup vs baseline: 1.1916x; 1.1890x over previous
#include <cuda_runtime.h>

#define THREADS 512
#define TT 30
#define RS 68   // row stride (swizzle padding)

typedef unsigned long long ull;

// ---------------- shared memory layout (float offsets) ----------------
#define W1T    0        // P1: W1' [80][256]=20480 ; P2: W3' [32][128]=4096
#define W2o    20480    // P1: W2' [96][128]=12288
#define W3T    0
#define W4o    4096     // P2: W4' [96][256]=24576
#define WOUTo  28672    // P2: Wout' [64][16]=1024
#define WIH3o  29696    // P2: Wih3' [32][128]=4096   (ends 33792)
#define B1o    33792    // 256  (interleaved [u][g])
#define B2o    34048    // 128
#define B3o    34176    // 128
#define B4o    34304    // 256
#define BOo    34560    // 16
// state [k][row] stride RS, rows swizzled: phys(r) = r + 4*(r>=32)
#define XINo   34576    // 2 x [16][68] = 2176
#define H1o    36752    // 2 x [64][68] = 8704   (P2: h4)
#define H2o    45456    // 2 x [32][68] = 4352   (P2: h3)
#define SHF    49808    // 199232 bytes

__device__ __forceinline__ void ffma2(ull &acc, ull a, ull b){
    asm("fma.rn.f32x2 %0, %1, %2, %0;" : "+l"(acc) : "l"(a), "l"(b));
}
__device__ __forceinline__ ull bcast2(float w){
    ull r; asm("mov.b64 %0, {%1, %1};" : "=l"(r) : "f"(w)); return r;
}
__device__ __forceinline__ ull pack2(float x, float y){
    ull r; asm("mov.b64 %0, {%1, %2};" : "=l"(r) : "f"(x), "f"(y)); return r;
}
__device__ __forceinline__ float2 unpack2(ull v){
    float2 f; asm("mov.b64 {%0, %1}, %2;" : "=f"(f.x), "=f"(f.y) : "l"(v)); return f;
}
__device__ __forceinline__ float ex2x(float x){
    float e; asm("ex2.approx.f32 %0, %1;" : "=f"(e) : "f"(x)); return e;
}
__device__ __forceinline__ float rcpx(float x){
    float r; asm("rcp.approx.f32 %0, %1;" : "=f"(r) : "f"(x)); return r;
}

// 8-MUFU LSTM activation (gate order i,f,g,o). Returns h, updates c.
__device__ __forceinline__ float act8(float zi, float zf, float zg, float zo, float &c){
    const float K1 = -1.4426950408889634f;
    float ei = ex2x(K1 * zi);
    float ef = ex2x(K1 * zf);
    float eg = ex2x(2.0f * K1 * zg);
    float eo = ex2x(K1 * zo);
    float A = 1.0f + ei, F = 1.0f + ef, G = 1.0f + eg, O = 1.0f + eo;
    float it = (1.0f - eg) * rcpx(A * G);
    float cn = fmaf(c, rcpx(F), it);
    float ec = ex2x(2.0f * K1 * cn);
    float C = 1.0f + ec;
    c = cn;
    return (1.0f - ec) * rcpx(O * C);
}

// acc[g][p] += sum_k W[k][u][g] * in[k][pr0+2p..]  (one unit per thread)
// in: SHARED [k][row] stride RS; W pre-offset to this thread's unit quad.
template<int NP, int NG>
__device__ __forceinline__ void accum(const float* __restrict__ in,
                                      const float* __restrict__ W,
                                      int K, ull (&acc)[4][NP], int pr0)
{
#pragma unroll 4
    for (int k = 0; k < K; k++) {
        ull hp[NP];
        {
            ulonglong2 hA = *reinterpret_cast<const ulonglong2*>(in + k*RS + pr0);
            hp[0] = hA.x; hp[1] = hA.y;
            if (NP == 4) {
                ulonglong2 hB = *reinterpret_cast<const ulonglong2*>(in + k*RS + pr0 + 4);
                hp[2] = hB.x; hp[3] = hB.y;
            }
        }
        float4 w = *reinterpret_cast<const float4*>(W + k*NG);
        ull w0 = bcast2(w.x), w1 = bcast2(w.y), w2 = bcast2(w.z), w3 = bcast2(w.w);
#pragma unroll
        for (int p = 0; p < NP; p++) {
            ffma2(acc[0][p], w0, hp[p]);
            ffma2(acc[1][p], w1, hp[p]);
            ffma2(acc[2][p], w2, hp[p]);
            ffma2(acc[3][p], w3, hp[p]);
        }
    }
}

template<int NP>
__device__ __forceinline__ void init_acc(ull (&acc)[4][NP], const ull (&b)[4]){
#pragma unroll
    for (int g = 0; g < 4; g++)
#pragma unroll
        for (int p = 0; p < NP; p++) acc[g][p] = b[g];
}

// activation; hdst pre-offset by u*RS.
template<int NP>
__device__ __forceinline__ void act_store(ull (&acc)[4][NP], float (&c)[2*NP],
                                          float* hdst, int pr0)
{
#pragma unroll
    for (int p = 0; p < NP; p++) {
        float2 zi = unpack2(acc[0][p]);
        float2 zf = unpack2(acc[1][p]);
        float2 zg = unpack2(acc[2][p]);
        float2 zo = unpack2(acc[3][p]);
        float h0 = act8(zi.x, zf.x, zg.x, zo.x, c[2*p]);
        float h1 = act8(zi.y, zf.y, zg.y, zo.y, c[2*p+1]);
        *reinterpret_cast<ull*>(hdst + pr0 + 2*p) = pack2(h0, h1);
    }
}

__global__ void __launch_bounds__(THREADS, 1)
lstm_ae(const float* __restrict__ x,
        const float* __restrict__ Wih1, const float* __restrict__ Whh1, const float* __restrict__ b1,
        const float* __restrict__ Wih2, const float* __restrict__ Whh2, const float* __restrict__ b2,
        const float* __restrict__ Wih3, const float* __restrict__ Whh3, const float* __restrict__ b3,
        const float* __restrict__ Wih4, const float* __restrict__ Whh4, const float* __restrict__ b4,
        const float* __restrict__ Wout, const float* __restrict__ bout,
        float* __restrict__ out)
{
    extern __shared__ float sh[];
    const int tid = threadIdx.x;
    const int wid = tid >> 5;
    const bool grpA = ((wid >> 2) & 1) == 0;   // SMSP w and w+4 alternate
    const long row0 = (long)blockIdx.x * 64;

    // H=64 layers: 1 unit x 8 rows
    const int uA  = tid >> 3;
    const int rA0 = (tid & 7) * 8;
    const int prA0 = rA0 + ((rA0 & 32) >> 3);
    // H=32 layers: 1 unit x 4 rows
    const int uB  = tid >> 4;
    const int rB0 = (tid & 15) * 4;
    const int prB0 = rB0 + ((rB0 & 32) >> 3);
    // x io: 1 row x 2 features
    const int xr  = tid >> 3;
    const int xf0 = (tid & 7) * 2;
    const int prx = xr + ((xr & 32) >> 3);
    // projection: 1 feature x 2 rows
    const int fo = tid & 15, rb = tid >> 4;
    const int rr = rb * 2;
    const int prb = rr + ((rr & 32) >> 3);

    // ---- phase-1 weights (interleaved [k][u][g]) + biases ----
    for (int i = tid; i < 20480; i += THREADS) {
        int k = i >> 8, j = i & 255, u = j >> 2, g = j & 3, row = g * 64 + u;
        sh[W1T + i] = (k < 16) ? Wih1[row * 16 + k] : Whh1[row * 64 + (k - 16)];
    }
    for (int i = tid; i < 12288; i += THREADS) {
        int k = i >> 7, j = i & 127, u = j >> 2, g = j & 3, row = g * 32 + u;
        sh[W2o + i] = (k < 64) ? Wih2[row * 64 + k] : Whh2[row * 32 + (k - 64)];
    }
    if (tid < 256) { int u = tid >> 2, g = tid & 3; sh[B1o + tid] = b1[g * 64 + u]; }
    if (tid < 128) { int u = tid >> 2, g = tid & 3; sh[B2o + tid] = b2[g * 32 + u]; }
    if (tid < 128) { int u = tid >> 2, g = tid & 3; sh[B3o + tid] = b3[g * 32 + u]; }
    if (tid < 256) { int u = tid >> 2, g = tid & 3; sh[B4o + tid] = b4[g * 64 + u]; }
    if (tid < 16)  sh[BOo + tid] = bout[tid];
    for (int i = tid; i < 4352; i += THREADS) sh[H1o + i] = 0.f;   // h1 buf0
    for (int i = tid; i < 2176; i += THREADS) sh[H2o + i] = 0.f;   // h2 buf0
    {   // x(0) -> XIN buf0
        float2 gx = *reinterpret_cast<const float2*>(x + (row0 + xr) * (TT * 16) + xf0);
        sh[XINo + (xf0    ) * RS + prx] = gx.x;
        sh[XINo + (xf0 + 1) * RS + prx] = gx.y;
    }
    __syncthreads();

    ull b1p[4], b2p[4];
#pragma unroll
    for (int g = 0; g < 4; g++) b1p[g] = bcast2(sh[B1o + uA * 4 + g]);
#pragma unroll
    for (int g = 0; g < 4; g++) b2p[g] = bcast2(sh[B2o + uB * 4 + g]);

    float c1[8], c2[4];
#pragma unroll
    for (int q = 0; q < 8; q++) c1[q] = 0.f;
#pragma unroll
    for (int q = 0; q < 4; q++) c2[q] = 0.f;

    // ---- phase 1: encoder. accL1 enters each t as b1 + Whh1@h1(t-1). ----
    ull accL1[4][4], accL2[4][2];
    init_acc<4>(accL1, b1p);                 // h1(-1) = 0

    for (int t = 0; t < TT; t++) {
        const int p = t & 1;
        float2 gx;
        const bool pf = (t + 1 < TT);
        if (pf) gx = *reinterpret_cast<const float2*>(
            x + (row0 + xr) * (TT * 16) + (t + 1) * 16 + xf0);
        accum<4, 256>(sh + XINo + p * (16 * RS), sh + W1T + uA * 4, 16, accL1, prA0);
        if (pf) {
            float* xb = sh + XINo + (p ^ 1) * (16 * RS);
            xb[(xf0    ) * RS + prx] = gx.x;
            xb[(xf0 + 1) * RS + prx] = gx.y;
        }
        if (grpA) {
            act_store<4>(accL1, c1, sh + H1o + (p ^ 1) * (64 * RS) + uA * RS, prA0);
            init_acc<2>(accL2, b2p);
            accum<2, 128>(sh + H2o + p * (32 * RS), sh + W2o + 64 * 128 + uB * 4, 32, accL2, prB0);
        } else {
            init_acc<2>(accL2, b2p);
            accum<2, 128>(sh + H2o + p * (32 * RS), sh + W2o + 64 * 128 + uB * 4, 32, accL2, prB0);
            act_store<4>(accL1, c1, sh + H1o + (p ^ 1) * (64 * RS) + uA * RS, prA0);
        }
        __syncthreads();
        accum<2, 128>(sh + H1o + (p ^ 1) * (64 * RS), sh + W2o + uB * 4, 64, accL2, prB0);
        if (grpA) {
            act_store<2>(accL2, c2, sh + H2o + (p ^ 1) * (32 * RS) + uB * RS, prB0);
            init_acc<4>(accL1, b1p);
            accum<4, 256>(sh + H1o + (p ^ 1) * (64 * RS), sh + W1T + 16 * 256 + uA * 4, 64, accL1, prA0);
        } else {
            init_acc<4>(accL1, b1p);
            accum<4, 256>(sh + H1o + (p ^ 1) * (64 * RS), sh + W1T + 16 * 256 + uA * 4, 64, accL1, prA0);
            act_store<2>(accL2, c2, sh + H2o + (p ^ 1) * (32 * RS) + uB * RS, prB0);
        }
        __syncthreads();
    }
    // latent = h2(29) in H2 buf 0

    // ---- phase-2 weights (overlay) ----
    for (int i = tid; i < 4096; i += THREADS) {
        int k = i >> 7, j = i & 127, u = j >> 2, g = j & 3, row = g * 32 + u;
        sh[W3T + i] = Whh3[row * 32 + k];
    }
    for (int i = tid; i < 24576; i += THREADS) {
        int k = i >> 8, j = i & 255, u = j >> 2, g = j & 3, row = g * 64 + u;
        sh[W4o + i] = (k < 32) ? Wih4[row * 32 + k] : Whh4[row * 64 + (k - 32)];
    }
    for (int i = tid; i < 1024; i += THREADS) {
        int jr = i >> 4, f = i & 15;
        sh[WOUTo + i] = Wout[f * 64 + jr];
    }
    for (int i = tid; i < 4096; i += THREADS) {
        int k = i >> 7, j = i & 127, u = j >> 2, g = j & 3, row = g * 32 + u;
        sh[WIH3o + i] = Wih3[row * 32 + k];
    }
    __syncthreads();

    // zin3 = Wih3 @ latent + b3 (constant over t), in registers
    ull zin3[4][2];
    {
        ull b3p[4];
#pragma unroll
        for (int g = 0; g < 4; g++) b3p[g] = bcast2(sh[B3o + uB * 4 + g]);
        init_acc<2>(zin3, b3p);
        accum<2, 128>(sh + H2o, sh + WIH3o + uB * 4, 32, zin3, prB0);
        __syncthreads();   // latent reads done before H2 reuse as h3
        for (int i = tid; i < 2176; i += THREADS) sh[H2o + i] = 0.f;  // h3 buf0
        for (int i = tid; i < 4352; i += THREADS) sh[H1o + i] = 0.f;  // h4 buf0
    }
    __syncthreads();

    ull b4p[4];
#pragma unroll
    for (int g = 0; g < 4; g++) b4p[g] = bcast2(sh[B4o + uA * 4 + g]);
    const float boutf = sh[BOo + fo];

    float c3[4], c4[8];
#pragma unroll
    for (int q = 0; q < 4; q++) c3[q] = 0.f;
#pragma unroll
    for (int q = 0; q < 8; q++) c4[q] = 0.f;

    // ---- phase 2: decoder. accL3 enters each t as zin3 + Whh3@h3(t-1). ----
    ull accL3[4][2], accL4[4][4];
#pragma unroll
    for (int g = 0; g < 4; g++)
#pragma unroll
        for (int pp = 0; pp < 2; pp++) accL3[g][pp] = zin3[g][pp];  // h3(-1)=0

    for (int t = 0; t < TT; t++) {
        const int p = t & 1;
        if (grpA) {
            act_store<2>(accL3, c3, sh + H2o + (p ^ 1) * (32 * RS) + uB * RS, prB0);
            init_acc<4>(accL4, b4p);
            accum<4, 256>(sh + H1o + p * (64 * RS), sh + W4o + 32 * 256 + uA * 4, 64, accL4, prA0);
        } else {
            init_acc<4>(accL4, b4p);
            accum<4, 256>(sh + H1o + p * (64 * RS), sh + W4o + 32 * 256 + uA * 4, 64, accL4, prA0);
        }
        if (t > 0) {   // projection of h4(t-1), overlapped
            const float* h4 = sh + H1o + p * (64 * RS);
            ull a0 = bcast2(boutf);
#pragma unroll 8
            for (int j = 0; j < 64; j++) {
                ull w  = bcast2(sh[WOUTo + j * 16 + fo]);
                ull hq = *reinterpret_cast<const ull*>(h4 + j * RS + prb);
                ffma2(a0, w, hq);
            }
            float2 y = unpack2(a0);
            long ob = (row0 + rr) * (TT * 16) + (t - 1) * 16 + fo;
            out[ob]           = y.x;
            out[ob + TT * 16] = y.y;
        }
        if (!grpA)
            act_store<2>(accL3, c3, sh + H2o + (p ^ 1) * (32 * RS) + uB * RS, prB0);
        __syncthreads();
        accum<4, 256>(sh + H2o + (p ^ 1) * (32 * RS), sh + W4o + uA * 4, 32, accL4, prA0);
        if (grpA) {
            act_store<4>(accL4, c4, sh + H1o + (p ^ 1) * (64 * RS) + uA * RS, prA0);
#pragma unroll
            for (int g = 0; g < 4; g++)
#pragma unroll
                for (int pp = 0; pp < 2; pp++) accL3[g][pp] = zin3[g][pp];
            accum<2, 128>(sh + H2o + (p ^ 1) * (32 * RS), sh + W3T + uB * 4, 32, accL3, prB0);
        } else {
#pragma unroll
            for (int g = 0; g < 4; g++)
#pragma unroll
                for (int pp = 0; pp < 2; pp++) accL3[g][pp] = zin3[g][pp];
            accum<2, 128>(sh + H2o + (p ^ 1) * (32 * RS), sh + W3T + uB * 4, 32, accL3, prB0);
            act_store<4>(accL4, c4, sh + H1o + (p ^ 1) * (64 * RS) + uA * RS, prA0);
        }
        __syncthreads();
    }
    // final projection: h4(29) in H1 buf 0
    {
        const float* h4 = sh + H1o;
        ull a0 = bcast2(boutf);
#pragma unroll 8
        for (int j = 0; j < 64; j++) {
            ull w  = bcast2(sh[WOUTo + j * 16 + fo]);
            ull hq = *reinterpret_cast<const ull*>(h4 + j * RS + prb);
            ffma2(a0, w, hq);
        }
        float2 y = unpack2(a0);
        long ob = (row0 + rr) * (TT * 16) + (TT - 1) * 16 + fo;
        out[ob]           = y.x;
        out[ob + TT * 16] = y.y;
    }
}

extern "C" void kernel_launch(void* const* d_in, const int* in_sizes, int n_in,
                              void* d_out, int out_size)
{
    const float* x    = (const float*)d_in[0];
    const float* Wih1 = (const float*)d_in[1];
    const float* Whh1 = (const float*)d_in[2];
    const float* b1   = (const float*)d_in[3];
    const float* Wih2 = (const float*)d_in[4];
    const float* Whh2 = (const float*)d_in[5];
    const float* b2   = (const float*)d_in[6];
    const float* Wih3 = (const float*)d_in[7];
    const float* Whh3 = (const float*)d_in[8];
    const float* b3   = (const float*)d_in[9];
    const float* Wih4 = (const float*)d_in[10];
    const float* Whh4 = (const float*)d_in[11];
    const float* b4   = (const float*)d_in[12];
    const float* Wout = (const float*)d_in[13];
    const float* bout = (const float*)d_in[14];
    float* out = (float*)d_out;

    cudaFuncSetAttribute(lstm_ae, cudaFuncAttributeMaxDynamicSharedMemorySize,
                         SHF * (int)sizeof(float));
    lstm_ae<<<128, THREADS, SHF * sizeof(float)>>>(
        x, Wih1, Whh1, b1, Wih2, Whh2, b2, Wih3, Whh3, b3,
        Wih4, Whh4, b4, Wout, bout, out);
}